// round 1
// baseline (speedup 1.0000x reference)
#include <cuda_runtime.h>
#include <math.h>

#define BB 8
#define NNODE 1024
#define FD 128
#define GD 64
#define EC 2
#define NH 4
#define NEDGE 16384
#define L0D 256
#define ROWS (BB*NNODE)   // 8192

// ---------------- scratch (static __device__, no allocation) ----------------
__device__ float g_adj[(size_t)BB*EC*NNODE*NNODE];   // 64 MB counts
__device__ float g_Wh[(size_t)BB*EC*NH*NNODE*GD];    // 16 MB
__device__ float g_q[BB*EC*NH*NNODE];
__device__ float g_v[BB*EC*NH*NNODE];
__device__ float g_Xsum[BB*FD];
__device__ float g_Swh[BB*EC*NH*GD];
__device__ float g_Hcat[(size_t)ROWS*512];           // 16 MB
__device__ float g_T1[ROWS*FD];
__device__ float g_H2[ROWS*FD];
__device__ float g_U[ROWS*L0D];
__device__ float g_Ue[ROWS*L0D];
__device__ float g_T3[ROWS*FD];
// stats layout: [0:128) sum1 [128:256) sq1 [256:512) sum2 [512:768) sq2 [768:896) sum3 [896:1024) sq3
__device__ float g_stats[1024];

// ---------------- kernels ----------------
__global__ void k_zero() {
    size_t i = (size_t)blockIdx.x * blockDim.x + threadIdx.x;  // 4M threads, 1 float4 each
    ((float4*)g_adj)[i] = make_float4(0.f, 0.f, 0.f, 0.f);
    if (blockIdx.x == 0) { g_stats[threadIdx.x] = 0.f; g_stats[threadIdx.x + 512] = 0.f; }
}

__global__ void k_scatter(const int* __restrict__ A) {
    int idx = blockIdx.x * blockDim.x + threadIdx.x;   // 262144 edges total
    int be = idx >> 14;
    int i  = idx & (NEDGE - 1);
    int src = A[(be * 2 + 0) * NEDGE + i];
    int dst = A[(be * 2 + 1) * NEDGE + i];
    atomicAdd(&g_adj[((size_t)be * NNODE + src) * NNODE + dst], 1.0f);
}

// Wh[b,e,h,n,g] = sum_f X[b,n,f] * Ws[e, h*128+f, g]
__global__ __launch_bounds__(256) void k_wh(const float* __restrict__ X, const float* __restrict__ Ws) {
    __shared__ float sX[32 * 129];
    __shared__ float sW[64 * 64];
    int nt = blockIdx.x;   // 0..31  (n tile)
    int b = blockIdx.y, e = blockIdx.z;
    int t = threadIdx.x;
    int row = t >> 3, gb = (t & 7) * 8;
    int n0 = nt * 32;
    for (int i = t; i < 32 * 128; i += 256) {
        int r = i >> 7, f = i & 127;
        sX[r * 129 + f] = X[((size_t)b * NNODE + n0 + r) * FD + f];
    }
    for (int h = 0; h < NH; h++) {
        float acc[8] = {0,0,0,0,0,0,0,0};
        for (int fc = 0; fc < 128; fc += 64) {
            __syncthreads();
            for (int i = t; i < 64 * 64; i += 256) {
                int f = i >> 6, g = i & 63;
                sW[f * 64 + g] = Ws[((size_t)e * 512 + h * 128 + fc + f) * GD + g];
            }
            __syncthreads();
#pragma unroll
            for (int f = 0; f < 64; f++) {
                float a = sX[row * 129 + fc + f];
#pragma unroll
                for (int c = 0; c < 8; c++) acc[c] += a * sW[f * 64 + gb + c];
            }
        }
        float* dst = g_Wh + (((size_t)(b * EC + e) * NH + h) * NNODE + (n0 + row)) * GD + gb;
#pragma unroll
        for (int c = 0; c < 8; c++) dst[c] = acc[c];
    }
}

// q[b,e,h,n] = X[b,n,:]·Wq[e,h,:],  same for v.  One warp per (b,n).
__global__ void k_qv(const float* __restrict__ X, const float* __restrict__ Wq,
                     const float* __restrict__ Wv) {
    int wid = blockIdx.x * 8 + (threadIdx.x >> 5);   // 0..8191
    int lane = threadIdx.x & 31;
    const float* xr = X + (size_t)wid * FD;
    float x0 = xr[lane * 4], x1 = xr[lane * 4 + 1], x2 = xr[lane * 4 + 2], x3 = xr[lane * 4 + 3];
    int b = wid >> 10, n = wid & 1023;
    for (int eh = 0; eh < EC * NH; eh++) {
        int e = eh >> 2, h = eh & 3;
        const float* wq = Wq + (e * 512 + h * 128);
        const float* wv = Wv + (e * 512 + h * 128);
        float pq = x0 * wq[lane*4] + x1 * wq[lane*4+1] + x2 * wq[lane*4+2] + x3 * wq[lane*4+3];
        float pv = x0 * wv[lane*4] + x1 * wv[lane*4+1] + x2 * wv[lane*4+2] + x3 * wv[lane*4+3];
        for (int off = 16; off; off >>= 1) {
            pq += __shfl_down_sync(0xffffffffu, pq, off);
            pv += __shfl_down_sync(0xffffffffu, pv, off);
        }
        if (lane == 0) {
            int idx = ((b * EC + e) * NH + h) * NNODE + n;
            g_q[idx] = pq; g_v[idx] = pv;
        }
    }
}

__global__ void k_xsum(const float* __restrict__ X) {
    int b = blockIdx.x, f = threadIdx.x;
    float s = 0.f;
    for (int n = 0; n < NNODE; n++) s += X[((size_t)b * NNODE + n) * FD + f];
    g_Xsum[b * FD + f] = s;
}

// Swh[b,e,h,g] = sum_f Xsum[b,f] * Ws[e,h*128+f,g]
__global__ void k_swh(const float* __restrict__ Ws) {
    int beh = blockIdx.x;          // b*8 + e*4 + h
    int g = threadIdx.x;
    int b = beh >> 3, e = (beh >> 2) & 1, h = beh & 3;
    float s = 0.f;
    for (int f = 0; f < FD; f++)
        s += g_Xsum[b * FD + f] * Ws[((size_t)e * 512 + h * 128 + f) * GD + g];
    g_Swh[beh * GD + g] = s;
}

// Sparse attention aggregation per (b,n). Threads: (h,g) = 4*64.
__global__ __launch_bounds__(256) void k_attn() {
    __shared__ int s_m[1024];
    __shared__ float s_c[1024];
    __shared__ int s_cnt;
    int bn = blockIdx.x;
    int b = bn >> 10, n = bn & 1023;
    int t = threadIdx.x;
    int h = t >> 6, g = t & 63;
    for (int e = 0; e < EC; e++) {
        if (t == 0) s_cnt = 0;
        __syncthreads();
        const float* arow = g_adj + ((size_t)(b * EC + e) * NNODE + n) * NNODE;
        for (int m = t; m < NNODE; m += 256) {
            float c = arow[m];
            if (c != 0.f) { int idx = atomicAdd(&s_cnt, 1); s_m[idx] = m; s_c[idx] = c; }
        }
        __syncthreads();
        int beh = (b * EC + e) * NH + h;
        float qn = g_q[beh * NNODE + n];
        const float* vb = g_v + beh * NNODE;
        const float* Whb = g_Wh + (size_t)beh * NNODE * GD;
        float num = 0.f, den = 0.f;
        int cnt = s_cnt;
        for (int j = 0; j < cnt; j++) {
            int m = s_m[j]; float c = s_c[j];
            float s = qn * vb[m] * c;
            float l = s >= 0.f ? s : 0.01f * s;
            float w = expf(l) - 1.f;
            den += w;
            num += w * Whb[m * GD + g];
        }
        float out = (g_Swh[beh * GD + g] + num) / (1024.f + den);
        g_Hcat[(size_t)bn * 512 + h * 128 + e * 64 + g] = out;
        __syncthreads();
    }
}

// Generic smem-tiled f32 GEMM  C[r,o] = sum_k A[r,k]*W[o,k]  with per-phase epilogue.
// PH0: A=g_Hcat K=512 NC=128 -> T1 = 0.5*relu + 0.5*X
// PH1: A=g_H2   K=128 NC=256 -> U
// PH2: A=g_Ue   K=256 NC=128 -> T3 = acc + H2
template <int PH>
__global__ __launch_bounds__(256) void k_gemm(const float* __restrict__ Wm,
                                              const float* __restrict__ X) {
    constexpr int K  = (PH == 0) ? 512 : (PH == 1) ? 128 : 256;
    constexpr int NC = (PH == 1) ? 256 : 128;
    const float* Amat = (PH == 0) ? g_Hcat : (PH == 1) ? g_H2 : g_Ue;
    float* Cm         = (PH == 0) ? g_T1   : (PH == 1) ? g_U  : g_T3;
    __shared__ float sA[32 * 65];
    __shared__ float sW[64 * 65];
    int r0 = blockIdx.x * 32, c0 = blockIdx.y * 64;
    int t = threadIdx.x;
    int row = t >> 3, cb = (t & 7) * 8;
    float acc[8] = {0,0,0,0,0,0,0,0};
    for (int kc = 0; kc < K; kc += 64) {
        for (int i = t; i < 2048; i += 256) {
            int r = i >> 6, k = i & 63;
            sA[r * 65 + k] = Amat[(size_t)(r0 + r) * K + kc + k];
        }
        for (int i = t; i < 4096; i += 256) {
            int c = i >> 6, k = i & 63;
            sW[k * 65 + c] = Wm[(size_t)(c0 + c) * K + kc + k];
        }
        __syncthreads();
#pragma unroll
        for (int k = 0; k < 64; k++) {
            float a = sA[row * 65 + k];
#pragma unroll
            for (int c = 0; c < 8; c++) acc[c] += a * sW[k * 65 + cb + c];
        }
        __syncthreads();
    }
    size_t rg = r0 + row;
#pragma unroll
    for (int c = 0; c < 8; c++) {
        int col = c0 + cb + c;
        float v = acc[c];
        if (PH == 0) v = 0.5f * fmaxf(v, 0.f) + 0.5f * X[rg * FD + col];
        if (PH == 2) v = v + g_H2[rg * FD + col];
        Cm[rg * NC + col] = v;
    }
}

// Column sum / sumsq over 8192 rows. PH0: T1/128 -> stats[0,128]; PH1: U/256 -> [256,512]; PH2: T3/128 -> [768,896]
template <int PH>
__global__ void k_colreduce() {
    constexpr int C = (PH == 1) ? 256 : 128;
    const float* src = (PH == 0) ? g_T1 : (PH == 1) ? g_U : g_T3;
    float* sum = g_stats + ((PH == 0) ? 0 : (PH == 1) ? 256 : 768);
    float* sq  = g_stats + ((PH == 0) ? 128 : (PH == 1) ? 512 : 896);
    __shared__ float sh[512];
    int t = threadIdx.x;
    int r0 = blockIdx.x * 128;
    if (C == 128) {
        int col = t & 127, rl = t >> 7;
        float s = 0.f, q = 0.f;
        for (int r = rl; r < 128; r += 2) {
            float v = src[(size_t)(r0 + r) * 128 + col];
            s += v; q += v * v;
        }
        sh[t] = s; sh[256 + t] = q;
        __syncthreads();
        if (t < 128) {
            atomicAdd(&sum[t], sh[t] + sh[t + 128]);
            atomicAdd(&sq[t],  sh[256 + t] + sh[384 + t]);
        }
    } else {
        int col = t;
        float s = 0.f, q = 0.f;
        for (int r = 0; r < 128; r++) {
            float v = src[(size_t)(r0 + r) * 256 + col];
            s += v; q += v * v;
        }
        atomicAdd(&sum[col], s);
        atomicAdd(&sq[col], q);
    }
}

__global__ void k_norm1() {  // H2 = bn(T1)
    int i = blockIdx.x * blockDim.x + threadIdx.x;
    int col = i & 127;
    float mu = g_stats[col] * (1.f / 8192.f);
    float var = g_stats[128 + col] * (1.f / 8192.f) - mu * mu;
    float rs = rsqrtf(var + 1e-5f);
    g_H2[i] = (g_T1[i] - mu) * rs;
}

__global__ void k_norm2() {  // Ue = elu(bn(U))
    int i = blockIdx.x * blockDim.x + threadIdx.x;
    int col = i & 255;
    float mu = g_stats[256 + col] * (1.f / 8192.f);
    float var = g_stats[512 + col] * (1.f / 8192.f) - mu * mu;
    float rs = rsqrtf(var + 1e-5f);
    float x = (g_U[i] - mu) * rs;
    g_Ue[i] = x > 0.f ? x : expm1f(x);
}

__global__ void k_norm3(float* __restrict__ out) {  // out = bn(T3)
    int i = blockIdx.x * blockDim.x + threadIdx.x;
    int col = i & 127;
    float mu = g_stats[768 + col] * (1.f / 8192.f);
    float var = g_stats[896 + col] * (1.f / 8192.f) - mu * mu;
    float rs = rsqrtf(var + 1e-5f);
    out[i] = (g_T3[i] - mu) * rs;
}

// ---------------- launch ----------------
extern "C" void kernel_launch(void* const* d_in, const int* in_sizes, int n_in,
                              void* d_out, int out_size) {
    const int*   A    = (const int*)d_in[0];
    const float* X    = (const float*)d_in[1];
    const float* Ws   = (const float*)d_in[2];
    const float* Wq   = (const float*)d_in[3];
    const float* Wv   = (const float*)d_in[4];
    const float* Wemb = (const float*)d_in[5];
    const float* Wl0  = (const float*)d_in[6];
    const float* Wl1  = (const float*)d_in[7];
    float* out = (float*)d_out;

    k_zero<<<8192, 512>>>();
    k_scatter<<<1024, 256>>>(A);
    k_wh<<<dim3(32, 8, 2), 256>>>(X, Ws);
    k_qv<<<1024, 256>>>(X, Wq, Wv);
    k_xsum<<<8, 128>>>(X);
    k_swh<<<64, 64>>>(Ws);
    k_attn<<<8192, 256>>>();
    k_gemm<0><<<dim3(256, 2), 256>>>(Wemb, X);
    k_colreduce<0><<<64, 256>>>();
    k_norm1<<<4096, 256>>>();
    k_gemm<1><<<dim3(256, 4), 256>>>(Wl0, nullptr);
    k_colreduce<1><<<64, 256>>>();
    k_norm2<<<8192, 256>>>();
    k_gemm<2><<<dim3(256, 2), 256>>>(Wl1, nullptr);
    k_colreduce<2><<<64, 256>>>();
    k_norm3<<<4096, 256>>>(out);
}